// round 5
// baseline (speedup 1.0000x reference)
#include <cuda_runtime.h>

// NaiveTemporalShift: x[B,T,N,C] fp32, U=1 -> channel partitions [0,86,171,256)
// with temporal shifts [-1, 0, +1]. out[b,t,n,c] = x[b, t-s(c), n, c] or 0.
//
// R4: persistent grid-stride kernel, exactly ONE wave (444 = 3*148 blocks,
// 512 threads). Each thread processes 4 chunks per iteration, loads batched
// before stores (MLP_p1=4). Removes block launch/retire churn and wave
// transitions; clean tail. Boundary chunks via vector blend.

#define TS_T 128
#define TS_N 21
#define TS_NC4  (TS_N * 256 / 4)                   // 1344 float4 per (b,t)
#define TS_TOTAL4 (64 * 128 * 21 * 256 / 4)        // 11,010,048 float4
#define TS_BLOCKS 444
#define TS_THREADS 512
#define TS_GS (TS_BLOCKS * TS_THREADS)             // 227,328

struct __align__(16) F4 { float x, y, z, w; };

__device__ __forceinline__ float4 ts_read_chunk(const float4* __restrict__ x4,
                                                const float* __restrict__ xf,
                                                int i) {
    unsigned row = (unsigned)i >> 6;              // (b*T + t)*N + n
    int c4 = i & 63;                              // float4 chunk within C=256
    int t = (int)((row / TS_N) & (TS_T - 1));

    int del;
    bool zero;
    if (c4 <= 21)      { del =  TS_NC4; zero = (t == TS_T - 1); }  // shift -1
    else if (c4 >= 42) { del = -TS_NC4; zero = (t == 0);        }  // shift +1
    else               { del = 0;       zero = false;           }  // copy

    float4 m = zero ? make_float4(0.f, 0.f, 0.f, 0.f) : x4[i + del];

    if (c4 == 21) {              // comps 2,3 are unshifted (copy partition)
        float4 p = x4[i];
        m.z = p.z; m.w = p.w;
    } else if (c4 == 42) {       // comps 0,1,2 are unshifted
        float4 p = x4[i];
        m.x = p.x; m.y = p.y; m.z = p.z;
    }
    return m;
}

__global__ void __launch_bounds__(TS_THREADS)
temporal_shift_kernel(const float* __restrict__ xf, float* __restrict__ outf) {
    const float4* __restrict__ x4 = reinterpret_cast<const float4*>(xf);
    float4* __restrict__ o4 = reinterpret_cast<float4*>(outf);

    int i = blockIdx.x * TS_THREADS + threadIdx.x;

    // Main loop: 4 chunks per iteration, loads batched then stores.
    while (i + 3 * TS_GS < TS_TOTAL4) {
        float4 m0 = ts_read_chunk(x4, xf, i);
        float4 m1 = ts_read_chunk(x4, xf, i + TS_GS);
        float4 m2 = ts_read_chunk(x4, xf, i + 2 * TS_GS);
        float4 m3 = ts_read_chunk(x4, xf, i + 3 * TS_GS);
        o4[i]             = m0;
        o4[i + TS_GS]     = m1;
        o4[i + 2 * TS_GS] = m2;
        o4[i + 3 * TS_GS] = m3;
        i += 4 * TS_GS;
    }
    // Residual (0..3 chunks per thread)
    while (i < TS_TOTAL4) {
        o4[i] = ts_read_chunk(x4, xf, i);
        i += TS_GS;
    }
}

extern "C" void kernel_launch(void* const* d_in, const int* in_sizes, int n_in,
                              void* d_out, int out_size) {
    const float* x = (const float*)d_in[0];
    float* out = (float*)d_out;
    temporal_shift_kernel<<<TS_BLOCKS, TS_THREADS>>>(x, out);
}

// round 6
// speedup vs baseline: 1.0240x; 1.0240x over previous
#include <cuda_runtime.h>

// NaiveTemporalShift: x[B,T,N,C] fp32, U=1 -> channel partitions [0,86,171,256)
// with temporal shifts [-1, 0, +1]. out[b,t,n,c] = x[b, t-s(c), n, c] or 0.
//
// R4: persistent grid-stride kernel, exactly ONE wave (444 = 3*148 blocks,
// 512 threads). Each thread processes 4 chunks per iteration, loads batched
// before stores (MLP_p1=4). Removes block launch/retire churn and wave
// transitions; clean tail. Boundary chunks via vector blend.

#define TS_T 128
#define TS_N 21
#define TS_NC4  (TS_N * 256 / 4)                   // 1344 float4 per (b,t)
#define TS_TOTAL4 (64 * 128 * 21 * 256 / 4)        // 11,010,048 float4
#define TS_BLOCKS 444
#define TS_THREADS 512
#define TS_GS (TS_BLOCKS * TS_THREADS)             // 227,328

struct __align__(16) F4 { float x, y, z, w; };

__device__ __forceinline__ float4 ts_read_chunk(const float4* __restrict__ x4,
                                                const float* __restrict__ xf,
                                                int i) {
    unsigned row = (unsigned)i >> 6;              // (b*T + t)*N + n
    int c4 = i & 63;                              // float4 chunk within C=256
    int t = (int)((row / TS_N) & (TS_T - 1));

    int del;
    bool zero;
    if (c4 <= 21)      { del =  TS_NC4; zero = (t == TS_T - 1); }  // shift -1
    else if (c4 >= 42) { del = -TS_NC4; zero = (t == 0);        }  // shift +1
    else               { del = 0;       zero = false;           }  // copy

    float4 m = zero ? make_float4(0.f, 0.f, 0.f, 0.f) : x4[i + del];

    if (c4 == 21) {              // comps 2,3 are unshifted (copy partition)
        float4 p = x4[i];
        m.z = p.z; m.w = p.w;
    } else if (c4 == 42) {       // comps 0,1,2 are unshifted
        float4 p = x4[i];
        m.x = p.x; m.y = p.y; m.z = p.z;
    }
    return m;
}

__global__ void __launch_bounds__(TS_THREADS)
temporal_shift_kernel(const float* __restrict__ xf, float* __restrict__ outf) {
    const float4* __restrict__ x4 = reinterpret_cast<const float4*>(xf);
    float4* __restrict__ o4 = reinterpret_cast<float4*>(outf);

    int i = blockIdx.x * TS_THREADS + threadIdx.x;

    // Main loop: 4 chunks per iteration, loads batched then stores.
    while (i + 3 * TS_GS < TS_TOTAL4) {
        float4 m0 = ts_read_chunk(x4, xf, i);
        float4 m1 = ts_read_chunk(x4, xf, i + TS_GS);
        float4 m2 = ts_read_chunk(x4, xf, i + 2 * TS_GS);
        float4 m3 = ts_read_chunk(x4, xf, i + 3 * TS_GS);
        o4[i]             = m0;
        o4[i + TS_GS]     = m1;
        o4[i + 2 * TS_GS] = m2;
        o4[i + 3 * TS_GS] = m3;
        i += 4 * TS_GS;
    }
    // Residual (0..3 chunks per thread)
    while (i < TS_TOTAL4) {
        o4[i] = ts_read_chunk(x4, xf, i);
        i += TS_GS;
    }
}

extern "C" void kernel_launch(void* const* d_in, const int* in_sizes, int n_in,
                              void* d_out, int out_size) {
    const float* x = (const float*)d_in[0];
    float* out = (float*)d_out;
    temporal_shift_kernel<<<TS_BLOCKS, TS_THREADS>>>(x, out);
}

// round 7
// speedup vs baseline: 1.1744x; 1.1469x over previous
#include <cuda_runtime.h>

// NaiveTemporalShift: x[B,T,N,C] fp32, U=1 -> channel partitions [0,86,171,256)
// with temporal shifts [-1, 0, +1]. out[b,t,n,c] = x[b, t-s(c), n, c] or 0.
//
// R5: R3 structure (best: 4 B-split float4 streams/thread, vector blend for
// the two misaligned boundary chunks, 512-thread blocks) + __stwt
// write-through stores: output has zero reuse, so bypass L2 dirty-line
// allocation and stream writes to DRAM, removing the end-of-kernel dirty
// drain that bleeds into the next graph replay.

#define TS_B 64
#define TS_T 128
#define TS_N 21
#define TS_C 256
#define TS_NC4  (TS_N * TS_C / 4)                  // 1344 float4 per (b,t)
#define TS_TOTAL4 (TS_B * TS_T * TS_N * TS_C / 4)  // 11,010,048 float4
#define TS_Q (TS_TOTAL4 / 4)                       // 2,752,512 (16 b's of float4)

__global__ void __launch_bounds__(512)
temporal_shift_kernel(const float* __restrict__ xf, float* __restrict__ outf) {
    int idx = blockIdx.x * 512 + threadIdx.x;   // in [0, TS_Q)

    const float4* __restrict__ x4 = reinterpret_cast<const float4*>(xf);
    float4* __restrict__ o4 = reinterpret_cast<float4*>(outf);

    unsigned row = (unsigned)idx >> 6;            // (b*T + t)*N + n, b in [0,16)
    int c4 = idx & 63;                            // float4 chunk within C=256
    int t = (int)((row / TS_N) & (TS_T - 1));     // shared by all 4 replicas

    // Primary (shifted) source offset and zero-fill predicate.
    // c4 <= 21 : shift -1 (read t+1), zero at t == T-1  (chunk 21: comps 0,1)
    // 22..41   : copy (del = 0)
    // c4 >= 42 : shift +1 (read t-1), zero at t == 0    (chunk 42: comp 3)
    int del;
    bool zero;
    if (c4 <= 21)      { del =  TS_NC4; zero = (t == TS_T - 1); }
    else if (c4 >= 42) { del = -TS_NC4; zero = (t == 0);        }
    else               { del = 0;       zero = false;           }

    const bool bndLo = (c4 == 21);   // comps 2,3 come from unshifted (copy)
    const bool bndHi = (c4 == 42);   // comps 0,1,2 come from unshifted (copy)

    const float4 zv = make_float4(0.f, 0.f, 0.f, 0.f);
    float4 m[4];

    // 4 independent shifted reads (front-batched, MLP_p1 = 4)
    #pragma unroll
    for (int k = 0; k < 4; k++)
        m[k] = zero ? zv : x4[idx + k * TS_Q + del];

    // Boundary blend: one lane per warp does one extra vector read per stream.
    if (bndLo) {
        #pragma unroll
        for (int k = 0; k < 4; k++) {
            float4 p = x4[idx + k * TS_Q];
            m[k].z = p.z; m[k].w = p.w;
        }
    } else if (bndHi) {
        #pragma unroll
        for (int k = 0; k < 4; k++) {
            float4 p = x4[idx + k * TS_Q];
            m[k].x = p.x; m[k].y = p.y; m[k].z = p.z;
        }
    }

    // Write-through streaming stores (no L2 dirty-line allocation).
    #pragma unroll
    for (int k = 0; k < 4; k++)
        __stwt(o4 + idx + k * TS_Q, m[k]);
}

extern "C" void kernel_launch(void* const* d_in, const int* in_sizes, int n_in,
                              void* d_out, int out_size) {
    const float* x = (const float*)d_in[0];
    float* out = (float*)d_out;
    int blocks = TS_Q / 512;   // 5376, exact
    temporal_shift_kernel<<<blocks, 512>>>(x, out);
}